// round 1
// baseline (speedup 1.0000x reference)
#include <cuda_runtime.h>
#include <cuda_bf16.h>
#include <cstdint>

// Problem constants (shape-specialized)
#define NY 496
#define NX 432
#define NZp 1
#define CCH 64
#define BATCH 4
#define SPATIAL (NY * NX * NZp)          // 214272
#define TOTAL_CELLS (BATCH * SPATIAL)    // 857088

// Scratch: per-cell winning voxel index (last-write-wins via atomicMax).
// 857088 * 4 B = 3.27 MB static device memory (allowed; no runtime allocs).
__device__ int g_winner[TOTAL_CELLS];

// K1: winner[] = -1, vectorized int4 (TOTAL_CELLS % 4 == 0)
__global__ void k_init_winner() {
    int i = blockIdx.x * blockDim.x + threadIdx.x;
    if (i < TOTAL_CELLS / 4) {
        reinterpret_cast<int4*>(g_winner)[i] = make_int4(-1, -1, -1, -1);
    }
}

// K2: for each voxel, atomicMax its index into its cell.
// coors row = [b, z, y, x] int32 -> int4 {x=b, y=z, z=y, w=x}
__global__ void k_vote(const int4* __restrict__ coors, int n) {
    int i = blockIdx.x * blockDim.x + threadIdx.x;
    if (i < n) {
        int4 c = coors[i];
        int g = c.x * SPATIAL + c.z * (NX * NZp) + c.w * NZp + c.y;
        atomicMax(&g_winner[g], i);
    }
}

// K3: tiled gather. One block = 32 spatial cells x 64 channels.
// - Feature reads: warp spans channels of one cell -> contiguous 128B.
// - Output writes: warp spans 32 consecutive spatial cells at fixed channel
//   -> contiguous 128B. Empty cells emit zeros (fused zero-fill).
__global__ __launch_bounds__(256) void k_gather(const float* __restrict__ feat,
                                                float* __restrict__ out) {
    __shared__ float tile[32][CCH + 1];   // +1 pad: conflict-free column reads
    __shared__ int   win[32];

    const int cell0 = blockIdx.x * 32;            // SPATIAL % 32 == 0 -> no batch straddle
    const int b     = cell0 / SPATIAL;
    const int s0    = cell0 - b * SPATIAL;
    const int tid   = threadIdx.x;

    if (tid < 32) win[tid] = g_winner[cell0 + tid];
    __syncthreads();

    // Phase A: fill tile. 4 cells in flight, 64 threads (one warp-pair) per cell.
    const int c   = tid & 63;
    const int grp = tid >> 6;                     // 0..3
#pragma unroll
    for (int j = 0; j < 8; ++j) {
        int cell = j * 4 + grp;
        int w    = win[cell];
        tile[cell][c] = (w >= 0) ? feat[w * CCH + c] : 0.0f;
    }
    __syncthreads();

    // Phase B: write out. warp = 32 consecutive spatial positions, fixed channel.
    const int s  = tid & 31;
    const int c0 = tid >> 5;                      // 0..7
    float* ob = out + (size_t)b * CCH * SPATIAL + (size_t)s0 + s;
#pragma unroll
    for (int k = 0; k < 8; ++k) {
        int cc = c0 + k * 8;
        ob[(size_t)cc * SPATIAL] = tile[s][cc];
    }
}

extern "C" void kernel_launch(void* const* d_in, const int* in_sizes, int n_in,
                              void* d_out, int out_size) {
    const float* feat  = (const float*)d_in[0];
    const int4*  coors = (const int4*)d_in[1];   // (N,4) int32, 16B rows
    float*       out   = (float*)d_out;

    const int n = in_sizes[0] / CCH;             // 320000

    k_init_winner<<<(TOTAL_CELLS / 4 + 255) / 256, 256>>>();
    k_vote<<<(n + 255) / 256, 256>>>(coors, n);
    k_gather<<<TOTAL_CELLS / 32, 256>>>(feat, out);
}

// round 4
// speedup vs baseline: 1.5691x; 1.5691x over previous
#include <cuda_runtime.h>
#include <cuda_bf16.h>
#include <cstdint>

// Problem constants (shape-specialized)
#define NY 496
#define NX 432
#define NZp 1
#define CCH 64
#define BATCH 4
#define SPATIAL (NY * NX * NZp)          // 214272
#define TOTAL_CELLS (BATCH * SPATIAL)    // 857088
#define CELLS_PER_BLK 64

// Per-cell winner voxel index + 1 (0 = empty). Static device globals are
// zero-initialized at module load; k_gather restores every nonzero entry to 0
// at the end of each call, so the all-zero invariant holds across graph
// replays (capture itself does not execute the kernels; every replay runs
// vote -> gather -> reset). 3.27 MB static scratch — no runtime allocation.
__device__ int g_winner[TOTAL_CELLS];

// K1: last-write-wins vote. coors row = [b, z, y, x] int32 -> int4{b,z,y,x}.
// Reference .at[gidx].set applies updates in index order => highest voxel
// index wins; atomicMax(i+1) reproduces that exactly.
__global__ void k_vote(const int4* __restrict__ coors, int n) {
    int i = blockIdx.x * blockDim.x + threadIdx.x;
    if (i < n) {
        int4 c = coors[i];
        int g = c.x * SPATIAL + c.z * (NX * NZp) + c.w * NZp + c.y;
        atomicMax(&g_winner[g], i + 1);
    }
}

// K2: tiled gather + transpose + fused zero-fill + winner reset.
// One block = 64 spatial cells x 64 channels (16 KB payload each way).
//  Phase A: 16 threads/cell LDG.128 the cell's 256B feature row (or zeros).
//  Phase B: each thread assembles a spatial-direction float4 and STG.128;
//           a warp writes 2 channels x 256B contiguous.
__global__ __launch_bounds__(256) void k_gather(const float4* __restrict__ feat4,
                                                float* __restrict__ out) {
    __shared__ float tile[CELLS_PER_BLK][65];  // stride 65: phase-B reads <=2-way conflict
    __shared__ int   win[CELLS_PER_BLK];

    const int cell0 = blockIdx.x * CELLS_PER_BLK;  // SPATIAL % 64 == 0: no batch straddle
    const int b     = cell0 / SPATIAL;
    const int s0    = cell0 - b * SPATIAL;
    const int tid   = threadIdx.x;

    int my_w = 0;
    if (tid < CELLS_PER_BLK) {
        my_w = g_winner[cell0 + tid];
        win[tid] = my_w;
    }
    __syncthreads();

    // Phase A: fill tile. 16 threads per cell, 16 cells per pass, 4 passes.
    const int v  = tid & 15;   // float4 index within the 64-ch row
    const int cg = tid >> 4;   // cell within pass
    int w0 = win[cg +  0];
    int w1 = win[cg + 16];
    int w2 = win[cg + 32];
    int w3 = win[cg + 48];
    float4 z = make_float4(0.f, 0.f, 0.f, 0.f);
    float4 f0 = w0 ? feat4[(size_t)(w0 - 1) * (CCH / 4) + v] : z;
    float4 f1 = w1 ? feat4[(size_t)(w1 - 1) * (CCH / 4) + v] : z;
    float4 f2 = w2 ? feat4[(size_t)(w2 - 1) * (CCH / 4) + v] : z;
    float4 f3 = w3 ? feat4[(size_t)(w3 - 1) * (CCH / 4) + v] : z;
    // restore invariant (off the critical load path)
    if (tid < CELLS_PER_BLK && my_w) g_winner[cell0 + tid] = 0;

    float* tr;
    tr = &tile[cg +  0][4 * v]; tr[0] = f0.x; tr[1] = f0.y; tr[2] = f0.z; tr[3] = f0.w;
    tr = &tile[cg + 16][4 * v]; tr[0] = f1.x; tr[1] = f1.y; tr[2] = f1.z; tr[3] = f1.w;
    tr = &tile[cg + 32][4 * v]; tr[0] = f2.x; tr[1] = f2.y; tr[2] = f2.z; tr[3] = f2.w;
    tr = &tile[cg + 48][4 * v]; tr[0] = f3.x; tr[1] = f3.y; tr[2] = f3.z; tr[3] = f3.w;
    __syncthreads();

    // Phase B: transpose out of smem, 128-bit coalesced stores.
    float* ob = out + (size_t)b * CCH * SPATIAL + s0;
#pragma unroll
    for (int q = 0; q < 4; ++q) {
        int i  = q * 256 + tid;
        int cc = i >> 4;            // channel 0..63
        int s  = (i & 15) * 4;      // spatial offset 0..60
        float4 o;
        o.x = tile[s + 0][cc];
        o.y = tile[s + 1][cc];
        o.z = tile[s + 2][cc];
        o.w = tile[s + 3][cc];
        *reinterpret_cast<float4*>(ob + (size_t)cc * SPATIAL + s) = o;
    }
}

extern "C" void kernel_launch(void* const* d_in, const int* in_sizes, int n_in,
                              void* d_out, int out_size) {
    const float4* feat4 = (const float4*)d_in[0];
    const int4*   coors = (const int4*)d_in[1];
    float*        out   = (float*)d_out;

    const int n = in_sizes[0] / CCH;  // 320000

    k_vote<<<(n + 255) / 256, 256>>>(coors, n);
    k_gather<<<TOTAL_CELLS / CELLS_PER_BLK, 256>>>(feat4, out);
}